// round 12
// baseline (speedup 1.0000x reference)
#include <cuda_runtime.h>
#include <cuda_bf16.h>
#include <stdint.h>

// ---------------------------------------------------------------------------
// TypeLoss — fused persistent kernel v3 (telescoping single-pass correction):
//   phase A1 (all blocks): for each relation, old = atomicOr(mask, bit);
//       if mask changed, add Q(old|bit) - Q(old==0 ? class0 : old) where
//       Q(m) = llrintf(loss(m) * 2^24). Telescopes EXACTLY (integer) to
//       Q(final_mask) - Q(class0) per row, any order -> deterministic.
//       Warp-reduced int64 -> 1 atomicAdd per warp.
//   barrier (grid-wide counter; single wave so all blocks resident)
//   phase A2 (all blocks): plain stores mask[flat] = 0 (replay invariant).
//   phase B  (all blocks): uniform contiguous stream of logits, class-0
//       closed form, unroll x4 coalesced; block tree reduction.
//   phase C: last block does fixed-order double finalize + state reset.
// ---------------------------------------------------------------------------

#define MAX_PAIRS   9000000          // >= 3000*2999 = 8,997,000
#define GRID        1184             // 8 * 148 SMs, single wave
#define NTHREADS    256
#define CORR_SCALE  16777216.0f      // 2^24 fixed point

__device__ unsigned int       g_mask32[MAX_PAIRS];  // zero at load; self-cleaning
__device__ float              g_partials[GRID];
__device__ unsigned long long g_corr;    // reset each replay by last block
__device__ unsigned int       g_count;   // finalize arrival counter
__device__ unsigned int       g_bar;     // grid barrier counter

__device__ __forceinline__ int pred_to_type(int pred) {
    if (pred == 1 || (pred >= 14 && pred <= 26)) return 1;
    if (pred >= 2 && pred <= 7)  return 2;
    if (pred >= 8 && pred <= 13) return 3;
    return 0;
}

__device__ __forceinline__ int flat_index(int i, int j, int insnum) {
    return i * (insnum - 1) + j - (i < j ? 1 : 0);
}

// class-0 row loss: -w0*(1-p0)^2*log(p0)
__device__ __forceinline__ float row_loss_base(float4 l, float w0) {
    float s = __expf(l.y - l.x) + __expf(l.z - l.x) + __expf(l.w - l.x);
    float t = 1.0f + s;
    float om = __fdividef(s, t);   // 1 - p0
    float lp = __logf(t);          // -log p0
    return w0 * om * om * lp;
}

// general masked focal loss for one row given precomputed exps
__device__ __forceinline__ float row_loss_mask(
    float e0, float e1, float e2, float e3, float S, unsigned m,
    float w0, float w1, float w2, float w3)
{
    float num = 0.0f, a = 0.0f;
    if (m & 1u) { num += e0; a += w0; }
    if (m & 2u) { num += e1; a += w1; }
    if (m & 4u) { num += e2; a += w2; }
    if (m & 8u) { num += e3; a += w3; }
    float p  = __fdividef(num, S);
    float om = 1.0f - p;
    return -a * om * om * __logf(p);
}

__global__ __launch_bounds__(NTHREADS, 8) void fused_kernel(
    const float4* __restrict__ logits,
    const int*    __restrict__ rel,
    const float*  __restrict__ pred_w,
    int n_rel, int insnum, int n_pairs,
    float* __restrict__ out)
{
    const int bid = blockIdx.x;
    const int tid = threadIdx.x;
    const int gthreads = GRID * NTHREADS;
    const float w0 = __ldg(&pred_w[0]);
    const float w1 = __ldg(&pred_w[1]);
    const float w2 = __ldg(&pred_w[2]);
    const float w3 = __ldg(&pred_w[3]);

    // ---------------- phase A1: telescoping scatter+correction ----------------
    long long q = 0;
    for (int r = bid * NTHREADS + tid; r < n_rel; r += gthreads) {
        int i    = rel[3 * r + 0];
        int j    = rel[3 * r + 1];
        int pred = rel[3 * r + 2];
        if (i == j) continue;
        if ((unsigned)i >= (unsigned)insnum ||
            (unsigned)j >= (unsigned)insnum) continue;
        int t = pred_to_type(pred < 0 ? 0 : (pred > 63 ? 63 : pred));
        int flat = flat_index(i, j, insnum);
        if ((unsigned)flat >= (unsigned)MAX_PAIRS) continue;

        unsigned bit = 1u << t;
        unsigned old = atomicOr(&g_mask32[flat], bit);
        unsigned nw  = old | bit;
        if (nw == old) continue;                  // duplicate: no transition

        float4 l = __ldg(&logits[flat]);
        float e0 = __expf(l.x);
        float e1 = __expf(l.y);
        float e2 = __expf(l.z);
        float e3 = __expf(l.w);
        float S  = (e0 + e1) + (e2 + e3);

        unsigned base = (old == 0u) ? 1u : old;   // empty row baseline = class0
        float lossN = row_loss_mask(e0, e1, e2, e3, S, nw,   w0, w1, w2, w3);
        float lossO = row_loss_mask(e0, e1, e2, e3, S, base, w0, w1, w2, w3);
        // Q(new) - Q(base): telescopes exactly in integer arithmetic
        q += llrintf(lossN * CORR_SCALE) - llrintf(lossO * CORR_SCALE);
    }
    // warp-reduce -> one atomic per warp
    #pragma unroll
    for (int off = 16; off > 0; off >>= 1)
        q += __shfl_xor_sync(0xffffffffu, q, off);
    if ((tid & 31) == 0 && q != 0)
        atomicAdd(&g_corr, (unsigned long long)q);

    // ---------------- grid barrier (all blocks resident) ----------------
    __threadfence();
    __syncthreads();
    if (tid == 0) {
        atomicAdd(&g_bar, 1u);
        volatile unsigned int* p = &g_bar;
        while (*p < (unsigned)GRID) __nanosleep(32);
    }
    __syncthreads();

    // ---------------- phase A2: cleanup (plain stores, idempotent) -----------
    for (int r = bid * NTHREADS + tid; r < n_rel; r += gthreads) {
        int i = rel[3 * r + 0];
        int j = rel[3 * r + 1];
        if (i == j) continue;
        if ((unsigned)i >= (unsigned)insnum ||
            (unsigned)j >= (unsigned)insnum) continue;
        int flat = flat_index(i, j, insnum);
        if ((unsigned)flat >= (unsigned)MAX_PAIRS) continue;
        g_mask32[flat] = 0u;
    }

    // ---------------- phase B: uniform logits stream ----------------
    int s  = (int)(((long long)n_pairs * bid) / GRID);
    int re = (int)(((long long)n_pairs * (bid + 1)) / GRID);

    float acc = 0.0f;
    int r = s + tid;
    for (; r + 3 * NTHREADS < re; r += 4 * NTHREADS) {
        float4 a = __ldcs(&logits[r]);
        float4 b = __ldcs(&logits[r +     NTHREADS]);
        float4 c = __ldcs(&logits[r + 2 * NTHREADS]);
        float4 d = __ldcs(&logits[r + 3 * NTHREADS]);
        acc += row_loss_base(a, w0);
        acc += row_loss_base(b, w0);
        acc += row_loss_base(c, w0);
        acc += row_loss_base(d, w0);
    }
    for (; r < re; r += NTHREADS)
        acc += row_loss_base(__ldcs(&logits[r]), w0);

    // deterministic block tree reduction
    __shared__ float sdata[NTHREADS];
    sdata[tid] = acc;
    __syncthreads();
    #pragma unroll
    for (int st = NTHREADS / 2; st > 0; st >>= 1) {
        if (tid < st) sdata[tid] += sdata[tid + st];
        __syncthreads();
    }

    __shared__ bool is_last;
    if (tid == 0) {
        g_partials[bid] = sdata[0];
        __threadfence();
        unsigned done = atomicAdd(&g_count, 1u);
        is_last = (done == (unsigned)GRID - 1u);
    }
    __syncthreads();
    if (!is_last) return;

    // ---------------- phase C: last-block finalize + state reset -------------
    __threadfence();
    __shared__ double ddata[NTHREADS];
    double dacc = 0.0;
    for (int k = tid; k < GRID; k += NTHREADS)
        dacc += (double)g_partials[k];
    ddata[tid] = dacc;
    __syncthreads();
    #pragma unroll
    for (int st = NTHREADS / 2; st > 0; st >>= 1) {
        if (tid < st) ddata[tid] += ddata[tid + st];
        __syncthreads();
    }
    if (tid == 0) {
        double total = ddata[0] +
            (double)(long long)g_corr * (1.0 / (double)CORR_SCALE);
        out[0] = (float)(total / (double)n_pairs);
        g_count = 0u;   // reset for next graph replay
        g_bar   = 0u;
        g_corr  = 0ULL;
    }
}

// ---------------------------------------------------------------------------
extern "C" void kernel_launch(void* const* d_in, const int* in_sizes, int n_in,
                              void* d_out, int out_size) {
    const float* type_output = (const float*)d_in[0];   // (n_pairs, 4) f32
    const int*   rel_gt      = (const int*)d_in[2];     // (n_rel, 3) int32
    const float* pred_w      = (const float*)d_in[3];   // (4,) f32

    int insnum  = in_sizes[1];
    int n_rel   = in_sizes[2] / 3;
    int n_pairs = insnum * insnum - insnum;

    fused_kernel<<<GRID, NTHREADS>>>(
        (const float4*)type_output, rel_gt, pred_w,
        n_rel, insnum, n_pairs, (float*)d_out);
}

// round 14
// speedup vs baseline: 1.0230x; 1.0230x over previous
#include <cuda_runtime.h>
#include <cuda_bf16.h>
#include <stdint.h>

// ---------------------------------------------------------------------------
// TypeLoss — fused persistent kernel v4 (barrier in the tail):
//   A1 (all blocks): scatter relations via atomicOr       (~1.5 us)
//   B  (all blocks): uniform logits stream, class-0 form  (~24 us, full chip)
//   barrier: counter barrier; arrival skew only (~1 us), scatter long done
//   A2 (all blocks): correction via atomicExch (unique winner, self-clean),
//                    warp-reduced int64 fixed point -> 1 atomic per warp
//   C: last block fixed-order double finalize + correction + state reset
// Deterministic: fixed partition, fixed-order sums, integer correction.
// ---------------------------------------------------------------------------

#define MAX_PAIRS   9000000          // >= 3000*2999 = 8,997,000
#define GRID        1184             // 8 * 148 SMs, single wave
#define NTHREADS    256
#define CORR_SCALE  16777216.0f      // 2^24 fixed point

__device__ unsigned int       g_mask32[MAX_PAIRS];  // zero at load; self-cleaning
__device__ float              g_partials[GRID];
__device__ unsigned long long g_corr;    // reset each replay by last block
__device__ unsigned int       g_count;   // finalize arrival counter
__device__ unsigned int       g_bar;     // grid barrier counter

__device__ __forceinline__ int pred_to_type(int pred) {
    if (pred == 1 || (pred >= 14 && pred <= 26)) return 1;
    if (pred >= 2 && pred <= 7)  return 2;
    if (pred >= 8 && pred <= 13) return 3;
    return 0;
}

__device__ __forceinline__ int flat_index(int i, int j, int insnum) {
    return i * (insnum - 1) + j - (i < j ? 1 : 0);
}

// class-0 row loss: -w0*(1-p0)^2*log(p0)
__device__ __forceinline__ float row_loss_base(float4 l, float w0) {
    float s = __expf(l.y - l.x) + __expf(l.z - l.x) + __expf(l.w - l.x);
    float t = 1.0f + s;
    float om = __fdividef(s, t);   // 1 - p0
    float lp = __logf(t);          // -log p0
    return w0 * om * om * lp;
}

__global__ __launch_bounds__(NTHREADS, 8) void fused_kernel(
    const float4* __restrict__ logits,
    const int*    __restrict__ rel,
    const float*  __restrict__ pred_w,
    int n_rel, int insnum, int n_pairs,
    float* __restrict__ out)
{
    const int bid = blockIdx.x;
    const int tid = threadIdx.x;
    const int gthreads = GRID * NTHREADS;
    const float w0 = __ldg(&pred_w[0]);

    // ---------------- A1: scatter (all blocks, tiny) ----------------
    for (int r = bid * NTHREADS + tid; r < n_rel; r += gthreads) {
        int i    = rel[3 * r + 0];
        int j    = rel[3 * r + 1];
        int pred = rel[3 * r + 2];
        if (i == j) continue;
        if ((unsigned)i >= (unsigned)insnum ||
            (unsigned)j >= (unsigned)insnum) continue;
        int t = pred_to_type(pred < 0 ? 0 : (pred > 63 ? 63 : pred));
        int flat = flat_index(i, j, insnum);
        if ((unsigned)flat >= (unsigned)MAX_PAIRS) continue;
        atomicOr(&g_mask32[flat], 1u << t);
    }

    // ---------------- B: uniform logits stream ----------------
    int s  = (int)(((long long)n_pairs * bid) / GRID);
    int re = (int)(((long long)n_pairs * (bid + 1)) / GRID);

    float acc = 0.0f;
    int r = s + tid;
    for (; r + 3 * NTHREADS < re; r += 4 * NTHREADS) {
        float4 a = __ldcs(&logits[r]);
        float4 b = __ldcs(&logits[r +     NTHREADS]);
        float4 c = __ldcs(&logits[r + 2 * NTHREADS]);
        float4 d = __ldcs(&logits[r + 3 * NTHREADS]);
        acc += row_loss_base(a, w0);
        acc += row_loss_base(b, w0);
        acc += row_loss_base(c, w0);
        acc += row_loss_base(d, w0);
    }
    for (; r < re; r += NTHREADS)
        acc += row_loss_base(__ldcs(&logits[r]), w0);

    // deterministic block tree reduction -> g_partials[bid]
    __shared__ float sdata[NTHREADS];
    sdata[tid] = acc;
    __syncthreads();
    #pragma unroll
    for (int st = NTHREADS / 2; st > 0; st >>= 1) {
        if (tid < st) sdata[tid] += sdata[tid + st];
        __syncthreads();
    }
    if (tid == 0) g_partials[bid] = sdata[0];

    // ---------------- barrier (tail; arrival skew only) ----------------
    __threadfence();
    __syncthreads();
    if (tid == 0) {
        atomicAdd(&g_bar, 1u);
        volatile unsigned int* p = &g_bar;
        while (*p < (unsigned)GRID) __nanosleep(32);
    }
    __syncthreads();

    // ---------------- A2: correction (unique winner, self-clean) ------------
    const float w1 = __ldg(&pred_w[1]);
    const float w2 = __ldg(&pred_w[2]);
    const float w3 = __ldg(&pred_w[3]);

    long long q = 0;
    for (int r2 = bid * NTHREADS + tid; r2 < n_rel; r2 += gthreads) {
        int i = rel[3 * r2 + 0];
        int j = rel[3 * r2 + 1];
        if (i == j) continue;
        if ((unsigned)i >= (unsigned)insnum ||
            (unsigned)j >= (unsigned)insnum) continue;
        int flat = flat_index(i, j, insnum);
        if ((unsigned)flat >= (unsigned)MAX_PAIRS) continue;

        unsigned m = atomicExch(&g_mask32[flat], 0u); // winner; self-clean
        if (m == 0u) continue;

        float4 l = __ldg(&logits[flat]);
        float e0 = __expf(l.x);
        float e1 = __expf(l.y);
        float e2 = __expf(l.z);
        float e3 = __expf(l.w);
        float S  = (e0 + e1) + (e2 + e3);

        float num = 0.0f, a = 0.0f;
        if (m & 1u) { num += e0; a += w0; }
        if (m & 2u) { num += e1; a += w1; }
        if (m & 4u) { num += e2; a += w2; }
        if (m & 8u) { num += e3; a += w3; }

        float pA  = __fdividef(num, S);
        float omA = 1.0f - pA;
        float lossA = -a * omA * omA * __logf(pA);
        float lossB = row_loss_base(l, w0);
        q += (long long)llrintf((lossA - lossB) * CORR_SCALE);
    }
    #pragma unroll
    for (int off = 16; off > 0; off >>= 1)
        q += __shfl_xor_sync(0xffffffffu, q, off);
    if ((tid & 31) == 0 && q != 0)
        atomicAdd(&g_corr, (unsigned long long)q);

    // ---------------- C: finalize (last block) ----------------
    __shared__ bool is_last;
    if (tid == 0) {
        __threadfence();
        unsigned done = atomicAdd(&g_count, 1u);
        is_last = (done == (unsigned)GRID - 1u);
    }
    __syncthreads();
    if (!is_last) return;

    __threadfence();
    __shared__ double ddata[NTHREADS];
    double dacc = 0.0;
    for (int k = tid; k < GRID; k += NTHREADS)
        dacc += (double)g_partials[k];
    ddata[tid] = dacc;
    __syncthreads();
    #pragma unroll
    for (int st = NTHREADS / 2; st > 0; st >>= 1) {
        if (tid < st) ddata[tid] += ddata[tid + st];
        __syncthreads();
    }
    if (tid == 0) {
        double total = ddata[0] +
            (double)(long long)g_corr * (1.0 / (double)CORR_SCALE);
        out[0] = (float)(total / (double)n_pairs);
        g_count = 0u;   // reset for next graph replay
        g_bar   = 0u;
        g_corr  = 0ULL;
    }
}

// ---------------------------------------------------------------------------
extern "C" void kernel_launch(void* const* d_in, const int* in_sizes, int n_in,
                              void* d_out, int out_size) {
    const float* type_output = (const float*)d_in[0];   // (n_pairs, 4) f32
    const int*   rel_gt      = (const int*)d_in[2];     // (n_rel, 3) int32
    const float* pred_w      = (const float*)d_in[3];   // (4,) f32

    int insnum  = in_sizes[1];
    int n_rel   = in_sizes[2] / 3;
    int n_pairs = insnum * insnum - insnum;

    fused_kernel<<<GRID, NTHREADS>>>(
        (const float4*)type_output, rel_gt, pred_w,
        n_rel, insnum, n_pairs, (float*)d_out);
}

// round 15
// speedup vs baseline: 1.0238x; 1.0008x over previous
#include <cuda_runtime.h>
#include <cuda_bf16.h>
#include <stdint.h>

// ---------------------------------------------------------------------------
// TypeLoss — fused persistent kernel v5 (barrier-free):
//   A1 (all blocks): ONE pass over relations. Generation-tagged mask word
//       [gen<<4 | mask4] updated via CAS loop; per successful transition
//       old->new add Q(new) - Q(old==0 ? class0 : old), Q(m)=llrintf(loss*2^24).
//       Telescopes exactly (integer) to Q(final)-Q(class0) per row in ANY
//       order -> deterministic. Warp-reduced int64 -> 1 atomicAdd per warp.
//       Stale generations read as empty => NO cleanup pass, NO barrier.
//   B  (all blocks): uniform logits stream, class-0 closed form, unroll x4.
//   C  (last block via g_count): fixed-order double finalize + g_corr,
//       reset g_corr/g_count, increment g_gen (invalidates mask lazily).
// ---------------------------------------------------------------------------

#define MAX_PAIRS   9000000          // >= 3000*2999 = 8,997,000
#define GRID        1184             // 8 * 148 SMs, single wave
#define NTHREADS    256
#define CORR_SCALE  16777216.0f     // 2^24 fixed point

__device__ unsigned int       g_mask32[MAX_PAIRS];  // [gen<<4 | mask]; lazy-invalidated
__device__ float              g_partials[GRID];
__device__ unsigned long long g_corr;    // reset each replay by last block
__device__ unsigned int       g_count;   // finalize arrival counter
__device__ unsigned int       g_gen;     // generation; ++ each replay

__device__ __forceinline__ int pred_to_type(int pred) {
    if (pred == 1 || (pred >= 14 && pred <= 26)) return 1;
    if (pred >= 2 && pred <= 7)  return 2;
    if (pred >= 8 && pred <= 13) return 3;
    return 0;
}

__device__ __forceinline__ int flat_index(int i, int j, int insnum) {
    return i * (insnum - 1) + j - (i < j ? 1 : 0);
}

// class-0 row loss: -w0*(1-p0)^2*log(p0)
__device__ __forceinline__ float row_loss_base(float4 l, float w0) {
    float s = __expf(l.y - l.x) + __expf(l.z - l.x) + __expf(l.w - l.x);
    float t = 1.0f + s;
    float om = __fdividef(s, t);   // 1 - p0
    float lp = __logf(t);          // -log p0
    return w0 * om * om * lp;
}

// masked focal loss for one row given precomputed exps
__device__ __forceinline__ float row_loss_mask(
    float e0, float e1, float e2, float e3, float S, unsigned m,
    float w0, float w1, float w2, float w3)
{
    float num = 0.0f, a = 0.0f;
    if (m & 1u) { num += e0; a += w0; }
    if (m & 2u) { num += e1; a += w1; }
    if (m & 4u) { num += e2; a += w2; }
    if (m & 8u) { num += e3; a += w3; }
    float p  = __fdividef(num, S);
    float om = 1.0f - p;
    return -a * om * om * __logf(p);
}

__global__ __launch_bounds__(NTHREADS, 8) void fused_kernel(
    const float4* __restrict__ logits,
    const int*    __restrict__ rel,
    const float*  __restrict__ pred_w,
    int n_rel, int insnum, int n_pairs,
    float* __restrict__ out)
{
    const int bid = blockIdx.x;
    const int tid = threadIdx.x;
    const int gthreads = GRID * NTHREADS;
    const float w0 = __ldg(&pred_w[0]);
    const float w1 = __ldg(&pred_w[1]);
    const float w2 = __ldg(&pred_w[2]);
    const float w3 = __ldg(&pred_w[3]);
    const unsigned gen = g_gen;               // stable during execution

    // -------- A1: single-pass scatter + telescoping correction --------
    long long q = 0;
    for (int r = bid * NTHREADS + tid; r < n_rel; r += gthreads) {
        int i    = rel[3 * r + 0];
        int j    = rel[3 * r + 1];
        int pred = rel[3 * r + 2];
        if (i == j) continue;
        if ((unsigned)i >= (unsigned)insnum ||
            (unsigned)j >= (unsigned)insnum) continue;
        int t = pred_to_type(pred < 0 ? 0 : (pred > 63 ? 63 : pred));
        int flat = flat_index(i, j, insnum);
        if ((unsigned)flat >= (unsigned)MAX_PAIRS) continue;

        unsigned bit = 1u << t;
        unsigned cur = g_mask32[flat];
        unsigned eff, nw;
        while (true) {
            eff = ((cur >> 4) == gen) ? (cur & 0xFu) : 0u;  // stale gen == empty
            nw  = eff | bit;
            if (nw == eff) { eff = nw; break; }             // duplicate: no write
            unsigned desired = (gen << 4) | nw;
            unsigned prev = atomicCAS(&g_mask32[flat], cur, desired);
            if (prev == cur) break;                         // won the transition
            cur = prev;                                     // retry
        }
        if (nw == eff) continue;                            // no transition

        float4 l = __ldg(&logits[flat]);
        float e0 = __expf(l.x);
        float e1 = __expf(l.y);
        float e2 = __expf(l.z);
        float e3 = __expf(l.w);
        float S  = (e0 + e1) + (e2 + e3);

        unsigned base = (eff == 0u) ? 1u : eff;             // empty -> class0
        float lossN = row_loss_mask(e0, e1, e2, e3, S, nw,   w0, w1, w2, w3);
        float lossO = row_loss_mask(e0, e1, e2, e3, S, base, w0, w1, w2, w3);
        q += llrintf(lossN * CORR_SCALE) - llrintf(lossO * CORR_SCALE);
    }
    // warp-reduce -> one atomic per warp
    #pragma unroll
    for (int off = 16; off > 0; off >>= 1)
        q += __shfl_xor_sync(0xffffffffu, q, off);
    if ((tid & 31) == 0 && q != 0)
        atomicAdd(&g_corr, (unsigned long long)q);

    // -------- B: uniform logits stream --------
    int s  = (int)(((long long)n_pairs * bid) / GRID);
    int re = (int)(((long long)n_pairs * (bid + 1)) / GRID);

    float acc = 0.0f;
    int r = s + tid;
    for (; r + 3 * NTHREADS < re; r += 4 * NTHREADS) {
        float4 a = __ldcs(&logits[r]);
        float4 b = __ldcs(&logits[r +     NTHREADS]);
        float4 c = __ldcs(&logits[r + 2 * NTHREADS]);
        float4 d = __ldcs(&logits[r + 3 * NTHREADS]);
        acc += row_loss_base(a, w0);
        acc += row_loss_base(b, w0);
        acc += row_loss_base(c, w0);
        acc += row_loss_base(d, w0);
    }
    for (; r < re; r += NTHREADS)
        acc += row_loss_base(__ldcs(&logits[r]), w0);

    // deterministic block tree reduction -> g_partials[bid]
    __shared__ float sdata[NTHREADS];
    sdata[tid] = acc;
    __syncthreads();
    #pragma unroll
    for (int st = NTHREADS / 2; st > 0; st >>= 1) {
        if (tid < st) sdata[tid] += sdata[tid + st];
        __syncthreads();
    }

    __shared__ bool is_last;
    if (tid == 0) {
        g_partials[bid] = sdata[0];
        __threadfence();
        unsigned done = atomicAdd(&g_count, 1u);
        is_last = (done == (unsigned)GRID - 1u);
    }
    __syncthreads();
    if (!is_last) return;

    // -------- C: last-block finalize + state rotate --------
    __threadfence();
    __shared__ double ddata[NTHREADS];
    double dacc = 0.0;
    for (int k = tid; k < GRID; k += NTHREADS)
        dacc += (double)g_partials[k];
    ddata[tid] = dacc;
    __syncthreads();
    #pragma unroll
    for (int st = NTHREADS / 2; st > 0; st >>= 1) {
        if (tid < st) ddata[tid] += ddata[tid + st];
        __syncthreads();
    }
    if (tid == 0) {
        double total = ddata[0] +
            (double)(long long)g_corr * (1.0 / (double)CORR_SCALE);
        out[0] = (float)(total / (double)n_pairs);
        g_count = 0u;            // reset for next graph replay
        g_corr  = 0ULL;
        g_gen   = (gen + 1u) & 0x0FFFFFFFu;  // lazily invalidate mask words
    }
}

// ---------------------------------------------------------------------------
extern "C" void kernel_launch(void* const* d_in, const int* in_sizes, int n_in,
                              void* d_out, int out_size) {
    const float* type_output = (const float*)d_in[0];   // (n_pairs, 4) f32
    const int*   rel_gt      = (const int*)d_in[2];     // (n_rel, 3) int32
    const float* pred_w      = (const float*)d_in[3];   // (4,) f32

    int insnum  = in_sizes[1];
    int n_rel   = in_sizes[2] / 3;
    int n_pairs = insnum * insnum - insnum;

    fused_kernel<<<GRID, NTHREADS>>>(
        (const float4*)type_output, rel_gt, pred_w,
        n_rel, insnum, n_pairs, (float*)d_out);
}

// round 17
// speedup vs baseline: 1.0807x; 1.0556x over previous
#include <cuda_runtime.h>
#include <cuda_bf16.h>
#include <stdint.h>

// ---------------------------------------------------------------------------
// TypeLoss — fused persistent kernel v6 (R9 overlap + v5 single-pass):
//   bids [0,592):   ONE pass over relations: gen-tagged CAS mask update,
//                   telescoping int64 fixed-point correction
//                   Q(new)-Q(old==0?class0:old); exact in any order.
//                   Warp-reduced -> 1 atomicAdd per warp. No spin, no cleanup
//                   (generation bump lazily invalidates mask each replay).
//                   Then stream with weight 960/1024.
//   bids [592,1184): stream logits IMMEDIATELY (keeps DRAM saturated at t=0).
//   stream: uniform class-0 closed form, unroll x4 coalesced.
//   finalize: last block (g_count) fixed-order double sum + g_corr, resets
//   g_count/g_corr, increments g_gen.
// Deterministic: fixed partition, fixed-order sums, integer correction.
// ---------------------------------------------------------------------------

#define MAX_PAIRS   9000000          // >= 3000*2999 = 8,997,000
#define GRID        1184             // 8 * 148 SMs, single wave
#define NTHREADS    256
#define ROLE_B      592              // role blocks [0, 592)
#define W_ROLE      960              // stream weight /1024 for role blocks
#define W_NORM      1024
#define CORR_SCALE  16777216.0f     // 2^24 fixed point

__device__ unsigned int       g_mask32[MAX_PAIRS];  // [gen<<4|mask]; lazy-invalidated
__device__ float              g_partials[GRID];
__device__ unsigned long long g_corr;    // reset each replay by last block
__device__ unsigned int       g_count;   // finalize arrival counter
__device__ unsigned int       g_gen;     // generation; ++ each replay

__device__ __forceinline__ int pred_to_type(int pred) {
    if (pred == 1 || (pred >= 14 && pred <= 26)) return 1;
    if (pred >= 2 && pred <= 7)  return 2;
    if (pred >= 8 && pred <= 13) return 3;
    return 0;
}

__device__ __forceinline__ int flat_index(int i, int j, int insnum) {
    return i * (insnum - 1) + j - (i < j ? 1 : 0);
}

// class-0 row loss: -w0*(1-p0)^2*log(p0)
__device__ __forceinline__ float row_loss_base(float4 l, float w0) {
    float s = __expf(l.y - l.x) + __expf(l.z - l.x) + __expf(l.w - l.x);
    float t = 1.0f + s;
    float om = __fdividef(s, t);   // 1 - p0
    float lp = __logf(t);          // -log p0
    return w0 * om * om * lp;
}

// masked focal loss for one row given precomputed exps
__device__ __forceinline__ float row_loss_mask(
    float e0, float e1, float e2, float e3, float S, unsigned m,
    float w0, float w1, float w2, float w3)
{
    float num = 0.0f, a = 0.0f;
    if (m & 1u) { num += e0; a += w0; }
    if (m & 2u) { num += e1; a += w1; }
    if (m & 4u) { num += e2; a += w2; }
    if (m & 8u) { num += e3; a += w3; }
    float p  = __fdividef(num, S);
    float om = 1.0f - p;
    return -a * om * om * __logf(p);
}

// cumulative integer stream weight of blocks [0, bid)
__device__ __forceinline__ long long cum_weight(int bid) {
    if (bid <= ROLE_B) return (long long)bid * W_ROLE;
    return (long long)ROLE_B * W_ROLE + (long long)(bid - ROLE_B) * W_NORM;
}

__global__ __launch_bounds__(NTHREADS, 8) void fused_kernel(
    const float4* __restrict__ logits,
    const int*    __restrict__ rel,
    const float*  __restrict__ pred_w,
    int n_rel, int insnum, int n_pairs,
    float* __restrict__ out)
{
    const int bid = blockIdx.x;
    const int tid = threadIdx.x;
    const float w0 = __ldg(&pred_w[0]);

    // -------- phase A (role blocks only): single-pass telescoping --------
    if (bid < ROLE_B) {
        const float w1 = __ldg(&pred_w[1]);
        const float w2 = __ldg(&pred_w[2]);
        const float w3 = __ldg(&pred_w[3]);
        const unsigned gen = g_gen;           // stable during execution

        long long q = 0;
        for (int r = bid * NTHREADS + tid; r < n_rel; r += ROLE_B * NTHREADS) {
            int i    = rel[3 * r + 0];
            int j    = rel[3 * r + 1];
            int pred = rel[3 * r + 2];
            if (i == j) continue;
            if ((unsigned)i >= (unsigned)insnum ||
                (unsigned)j >= (unsigned)insnum) continue;
            int t = pred_to_type(pred < 0 ? 0 : (pred > 63 ? 63 : pred));
            int flat = flat_index(i, j, insnum);
            if ((unsigned)flat >= (unsigned)MAX_PAIRS) continue;

            unsigned bit = 1u << t;
            unsigned cur = g_mask32[flat];
            unsigned eff, nw;
            while (true) {
                eff = ((cur >> 4) == gen) ? (cur & 0xFu) : 0u;  // stale == empty
                nw  = eff | bit;
                if (nw == eff) break;                           // duplicate
                unsigned desired = (gen << 4) | nw;
                unsigned prev = atomicCAS(&g_mask32[flat], cur, desired);
                if (prev == cur) break;                         // won transition
                cur = prev;                                     // retry
            }
            if (nw == eff) continue;                            // no transition

            float4 l = __ldg(&logits[flat]);
            float e0 = __expf(l.x);
            float e1 = __expf(l.y);
            float e2 = __expf(l.z);
            float e3 = __expf(l.w);
            float S  = (e0 + e1) + (e2 + e3);

            unsigned base = (eff == 0u) ? 1u : eff;             // empty->class0
            float lossN = row_loss_mask(e0, e1, e2, e3, S, nw,   w0, w1, w2, w3);
            float lossO = row_loss_mask(e0, e1, e2, e3, S, base, w0, w1, w2, w3);
            q += llrintf(lossN * CORR_SCALE) - llrintf(lossO * CORR_SCALE);
        }
        #pragma unroll
        for (int off = 16; off > 0; off >>= 1)
            q += __shfl_xor_sync(0xffffffffu, q, off);
        if ((tid & 31) == 0 && q != 0)
            atomicAdd(&g_corr, (unsigned long long)q);
    }

    // -------- phase B: logits stream (skew-weighted static partition) --------
    const long long TW = cum_weight(GRID);
    int s  = (int)(((long long)n_pairs * cum_weight(bid)) / TW);
    int re = (int)(((long long)n_pairs * cum_weight(bid + 1)) / TW);

    float acc = 0.0f;
    int r = s + tid;
    for (; r + 3 * NTHREADS < re; r += 4 * NTHREADS) {
        float4 a = __ldcs(&logits[r]);
        float4 b = __ldcs(&logits[r +     NTHREADS]);
        float4 c = __ldcs(&logits[r + 2 * NTHREADS]);
        float4 d = __ldcs(&logits[r + 3 * NTHREADS]);
        acc += row_loss_base(a, w0);
        acc += row_loss_base(b, w0);
        acc += row_loss_base(c, w0);
        acc += row_loss_base(d, w0);
    }
    for (; r < re; r += NTHREADS)
        acc += row_loss_base(__ldcs(&logits[r]), w0);

    // deterministic block tree reduction -> g_partials[bid]
    __shared__ float sdata[NTHREADS];
    sdata[tid] = acc;
    __syncthreads();
    #pragma unroll
    for (int st = NTHREADS / 2; st > 0; st >>= 1) {
        if (tid < st) sdata[tid] += sdata[tid + st];
        __syncthreads();
    }

    __shared__ bool is_last;
    if (tid == 0) {
        g_partials[bid] = sdata[0];
        __threadfence();
        unsigned done = atomicAdd(&g_count, 1u);
        is_last = (done == (unsigned)GRID - 1u);
    }
    __syncthreads();
    if (!is_last) return;

    // -------- finalize: last block, fixed order; rotate state --------
    __threadfence();
    __shared__ double ddata[NTHREADS];
    double dacc = 0.0;
    for (int k = tid; k < GRID; k += NTHREADS)
        dacc += (double)g_partials[k];
    ddata[tid] = dacc;
    __syncthreads();
    #pragma unroll
    for (int st = NTHREADS / 2; st > 0; st >>= 1) {
        if (tid < st) ddata[tid] += ddata[tid + st];
        __syncthreads();
    }
    if (tid == 0) {
        double total = ddata[0] +
            (double)(long long)g_corr * (1.0 / (double)CORR_SCALE);
        out[0] = (float)(total / (double)n_pairs);
        g_count = 0u;                          // reset for next graph replay
        g_corr  = 0ULL;
        g_gen   = (g_gen + 1u) & 0x0FFFFFFFu;  // lazily invalidate mask words
    }
}

// ---------------------------------------------------------------------------
extern "C" void kernel_launch(void* const* d_in, const int* in_sizes, int n_in,
                              void* d_out, int out_size) {
    const float* type_output = (const float*)d_in[0];   // (n_pairs, 4) f32
    const int*   rel_gt      = (const int*)d_in[2];     // (n_rel, 3) int32
    const float* pred_w      = (const float*)d_in[3];   // (4,) f32

    int insnum  = in_sizes[1];
    int n_rel   = in_sizes[2] / 3;
    int n_pairs = insnum * insnum - insnum;

    fused_kernel<<<GRID, NTHREADS>>>(
        (const float4*)type_output, rel_gt, pred_w,
        n_rel, insnum, n_pairs, (float*)d_out);
}